// round 15
// baseline (speedup 1.0000x reference)
#include <cuda_runtime.h>
#include <cstdint>
#include <cstddef>

#define BATCHES 16
#define NPTS    65536
#define NSAMP   2048
#define CPB     8                    // CTAs per batch = cluster size
#define NPC     (NPTS / CPB)         // 8192 points per CTA
#define THREADS 1024
#define NWARPS  (THREADS / 32)       // 32
#define PPT     (NPC / THREADS)      // 8 consecutive points per thread
#define NPAIR   (PPT / 2)            // 4 packed point-pairs per thread

// dynamic smem: local copy of this CTA's coords (winner lookup only)
#define SMEM_BYTES (3 * NPC * 4)     // 96 KB

typedef unsigned long long u64;

// ---- packed f32x2 helpers (per-lane IEEE .rn — bit-identical to scalar) ----
static __device__ __forceinline__ u64 pack2_(float lo, float hi) {
    u64 r; asm("mov.b64 %0, {%1, %2};" : "=l"(r) : "f"(lo), "f"(hi)); return r;
}
static __device__ __forceinline__ void unpack2_(u64 v, float& lo, float& hi) {
    asm("mov.b64 {%0, %1}, %2;" : "=f"(lo), "=f"(hi) : "l"(v));
}
static __device__ __forceinline__ u64 add2_(u64 a, u64 b) {
    u64 r; asm("add.rn.f32x2 %0, %1, %2;" : "=l"(r) : "l"(a), "l"(b)); return r;
}
static __device__ __forceinline__ u64 mul2_(u64 a, u64 b) {
    u64 r; asm("mul.rn.f32x2 %0, %1, %2;" : "=l"(r) : "l"(a), "l"(b)); return r;
}
static __device__ __forceinline__ u64 fma2_(u64 a, u64 b, u64 c) {
    u64 r; asm("fma.rn.f32x2 %0, %1, %2, %3;" : "=l"(r) : "l"(a), "l"(b), "l"(c)); return r;
}

static __device__ __forceinline__ unsigned cluster_rank_() {
    unsigned r;
    asm("mov.u32 %0, %%cluster_ctarank;" : "=r"(r));
    return r;
}
static __device__ __forceinline__ unsigned mapa_shared_(unsigned addr, unsigned target) {
    unsigned r;
    asm("mapa.shared::cluster.u32 %0, %1, %2;" : "=r"(r) : "r"(addr), "r"(target));
    return r;
}
static __device__ __forceinline__ void st_cluster_v4_(unsigned addr, unsigned a, unsigned b,
                                                      unsigned c, unsigned d) {
    asm volatile("st.shared::cluster.v4.b32 [%0], {%1,%2,%3,%4};"
                 :: "r"(addr), "r"(a), "r"(b), "r"(c), "r"(d) : "memory");
}
static __device__ __forceinline__ void st_cluster_b32_(unsigned addr, unsigned a) {
    asm volatile("st.shared::cluster.b32 [%0], %1;"
                 :: "r"(addr), "r"(a) : "memory");
}
static __device__ __forceinline__ void cluster_sync_() {
    asm volatile("barrier.cluster.arrive.aligned;" ::: "memory");
    asm volatile("barrier.cluster.wait.aligned;" ::: "memory");
}

__global__ void __launch_bounds__(THREADS, 1) __cluster_dims__(CPB, 1, 1)
fps_kernel(const float* __restrict__ t_in, float* __restrict__ out)
{
    extern __shared__ float sm[];
    float* spx = sm;
    float* spy = sm + NPC;
    float* spz = sm + 2 * NPC;

    // Double-buffered cluster slot exchange: [buf][src_rank][8] = {val, idx, x, y, z,...}
    __shared__ __align__(16) float s_slots[2][CPB][8];
    __shared__ unsigned s_v[NWARPS];
    __shared__ unsigned s_i[NWARPS];

    const int tid  = threadIdx.x;
    const int lane = tid & 31;
    const int warp = tid >> 5;
    const unsigned rank = cluster_rank_();
    const int batch = blockIdx.x / CPB;

    const float* __restrict__ pb = t_in + (size_t)batch * ((size_t)NPTS * 3);

    // ---- load my 8 consecutive points into packed register pairs + smem copy ----
    const int base = (int)rank * NPC + tid * PPT;   // within-batch global index
    u64 px2[NPAIR], py2[NPAIR], pz2[NPAIR];
    float dist[PPT];
    {
        const float4* p4 = (const float4*)(pb + (size_t)base * 3);  // 96B stride, 16B aligned
        float c[PPT * 3];
        #pragma unroll
        for (int q = 0; q < (PPT * 3) / 4; q++) {
            float4 v = __ldg(p4 + q);
            c[4 * q + 0] = v.x; c[4 * q + 1] = v.y;
            c[4 * q + 2] = v.z; c[4 * q + 3] = v.w;
        }
        #pragma unroll
        for (int q = 0; q < NPAIR; q++) {
            px2[q] = pack2_(c[6 * q + 0], c[6 * q + 3]);
            py2[q] = pack2_(c[6 * q + 1], c[6 * q + 4]);
            pz2[q] = pack2_(c[6 * q + 2], c[6 * q + 5]);
        }
        #pragma unroll
        for (int j = 0; j < PPT; j++) {
            dist[j] = 1e10f;
            int li = tid * PPT + j;
            spx[li] = c[3 * j]; spy[li] = c[3 * j + 1]; spz[li] = c[3 * j + 2];
        }
    }

    // First sample is always index 0; its coords seed the loop.
    float lx = __ldg(pb + 0), ly = __ldg(pb + 1), lz = __ldg(pb + 2);
    if (rank == 0 && tid == 0) out[batch * NSAMP] = 0.0f;
    __syncthreads();

    const unsigned slots_u32 =
        (unsigned)__cvta_generic_to_shared(&s_slots[0][0][0]);

    for (int k = 1; k < NSAMP; k++) {
        // ---- packed distance update: 2 points per instruction ----
        const u64 nlx = pack2_(-lx, -lx);
        const u64 nly = pack2_(-ly, -ly);
        const u64 nlz = pack2_(-lz, -lz);

        unsigned bbits[PPT];
        #pragma unroll
        for (int q = 0; q < NPAIR; q++) {
            u64 dx2 = add2_(px2[q], nlx);
            u64 dy2 = add2_(py2[q], nly);
            u64 dz2 = add2_(pz2[q], nlz);
            // d = fma(dz,dz, fma(dy,dy, dx*dx)) per lane — bit-identical to ref.
            u64 d2  = fma2_(dz2, dz2, fma2_(dy2, dy2, mul2_(dx2, dx2)));
            float dlo, dhi;
            unpack2_(d2, dlo, dhi);
            float n0 = fminf(dist[2 * q + 0], dlo); dist[2 * q + 0] = n0;
            float n1 = fminf(dist[2 * q + 1], dhi); dist[2 * q + 1] = n1;
            bbits[2 * q + 0] = __float_as_uint(n0);   // dist>=0: uint order == float
            bbits[2 * q + 1] = __float_as_uint(n1);
        }

        // ---- per-thread argmax: 3-level max tree + parallel mask + ffs ----
        unsigned m01 = max(bbits[0], bbits[1]);
        unsigned m23 = max(bbits[2], bbits[3]);
        unsigned m45 = max(bbits[4], bbits[5]);
        unsigned m67 = max(bbits[6], bbits[7]);
        unsigned vb  = max(max(m01, m23), max(m45, m67));
        unsigned msk = 0u;
        #pragma unroll
        for (int j = 0; j < PPT; j++)
            msk |= (bbits[j] == vb) ? (1u << j) : 0u;
        int bestj = __ffs(msk) - 1;                    // smallest j == first max
        int gidx  = base + bestj;

        // ---- warp argmax: redux + ballot + ffs (lowest lane == lowest index) ----
        unsigned vmax = __reduce_max_sync(0xffffffffu, vb);
        unsigned eq   = __ballot_sync(0xffffffffu, vb == vmax);
        int      src  = __ffs(eq) - 1;
        int      widx = __shfl_sync(0xffffffffu, gidx, src);
        if (lane == 0) { s_v[warp] = vmax; s_i[warp] = (unsigned)widx; }
        __syncthreads();

        // ---- warp 0: CTA argmax over 32 warps, push slot into all 8 CTAs ----
        if (warp == 0) {
            unsigned v  = s_v[lane];                        // 32 warps == 32 lanes
            unsigned vm = __reduce_max_sync(0xffffffffu, v);
            unsigned e2 = __ballot_sync(0xffffffffu, v == vm);
            int      s2 = __ffs(e2) - 1;                    // warps asc == index asc
            unsigned ii = s_i[lane];
            unsigned cidx = __shfl_sync(0xffffffffu, ii, s2);

            if (lane < CPB) {
                int li = (int)cidx - (int)rank * NPC;       // winner is CTA-local
                unsigned xb = __float_as_uint(spx[li]);
                unsigned yb = __float_as_uint(spy[li]);
                unsigned zb = __float_as_uint(spz[li]);
                unsigned la = slots_u32 + (((unsigned)(k & 1) * CPB + rank) * 8u) * 4u;
                unsigned ra = mapa_shared_(la, (unsigned)lane);
                st_cluster_v4_(ra, vm, __float_as_uint(__uint2float_rn(cidx)), xb, yb);
                st_cluster_b32_(ra + 16u, zb);
            }
        }
        // barrier.cluster: arrive releases the DSMEM stores, wait acquires them.
        cluster_sync_();

        // ---- all threads: tree-scan the 8 local slots for the batch winner ----
        const unsigned* ss = (const unsigned*)&s_slots[k & 1][0][0];
        unsigned sv[CPB];
        #pragma unroll
        for (int s = 0; s < CPB; s++) sv[s] = ss[s * 8];
        unsigned t01 = max(sv[0], sv[1]);
        unsigned t23 = max(sv[2], sv[3]);
        unsigned t45 = max(sv[4], sv[5]);
        unsigned t67 = max(sv[6], sv[7]);
        unsigned tmx = max(max(t01, t23), max(t45, t67));
        unsigned sm2 = 0u;
        #pragma unroll
        for (int s = 0; s < CPB; s++)
            sm2 |= (sv[s] == tmx) ? (1u << s) : 0u;
        int bs = __ffs(sm2) - 1;                       // lowest rank wins tie

        const float* w = &s_slots[k & 1][bs][0];
        lx = w[2]; ly = w[3]; lz = w[4];

        if (rank == 0 && tid == 0) out[batch * NSAMP + k] = w[1];
    }
}

extern "C" void kernel_launch(void* const* d_in, const int* in_sizes, int n_in,
                              void* d_out, int out_size)
{
    // t_in is the largest input under any size convention.
    int best = 0;
    for (int i = 1; i < n_in; i++)
        if (in_sizes[i] > in_sizes[best]) best = i;
    const float* t_in = (const float*)d_in[best];

    // Not a stream op; graph-capture safe.
    cudaFuncSetAttribute(fps_kernel, cudaFuncAttributeMaxDynamicSharedMemorySize,
                         SMEM_BYTES);

    fps_kernel<<<BATCHES * CPB, THREADS, SMEM_BYTES>>>(t_in, (float*)d_out);
}

// round 16
// speedup vs baseline: 1.1174x; 1.1174x over previous
#include <cuda_runtime.h>
#include <cstdint>
#include <cstddef>

#define BATCHES 16
#define NPTS    65536
#define NSAMP   2048
#define CPB     8                    // CTAs per batch = cluster size
#define NPC     (NPTS / CPB)         // 8192 points per CTA
#define THREADS 512
#define NWARPS  (THREADS / 32)       // 16
#define PPT     (NPC / THREADS)      // 16 consecutive points per thread
#define NPAIR   (PPT / 2)            // 8 packed point-pairs per thread

// dynamic smem: local copy of this CTA's coords (winner lookup only)
#define SMEM_BYTES (3 * NPC * 4)     // 96 KB

typedef unsigned long long u64;

// ---- packed f32x2 helpers (per-lane IEEE .rn — bit-identical to scalar) ----
static __device__ __forceinline__ u64 pack2_(float lo, float hi) {
    u64 r; asm("mov.b64 %0, {%1, %2};" : "=l"(r) : "f"(lo), "f"(hi)); return r;
}
static __device__ __forceinline__ void unpack2_(u64 v, float& lo, float& hi) {
    asm("mov.b64 {%0, %1}, %2;" : "=f"(lo), "=f"(hi) : "l"(v));
}
static __device__ __forceinline__ u64 add2_(u64 a, u64 b) {
    u64 r; asm("add.rn.f32x2 %0, %1, %2;" : "=l"(r) : "l"(a), "l"(b)); return r;
}
static __device__ __forceinline__ u64 mul2_(u64 a, u64 b) {
    u64 r; asm("mul.rn.f32x2 %0, %1, %2;" : "=l"(r) : "l"(a), "l"(b)); return r;
}
static __device__ __forceinline__ u64 fma2_(u64 a, u64 b, u64 c) {
    u64 r; asm("fma.rn.f32x2 %0, %1, %2, %3;" : "=l"(r) : "l"(a), "l"(b), "l"(c)); return r;
}

static __device__ __forceinline__ unsigned cluster_rank_() {
    unsigned r;
    asm("mov.u32 %0, %%cluster_ctarank;" : "=r"(r));
    return r;
}
static __device__ __forceinline__ unsigned mapa_shared_(unsigned addr, unsigned target) {
    unsigned r;
    asm("mapa.shared::cluster.u32 %0, %1, %2;" : "=r"(r) : "r"(addr), "r"(target));
    return r;
}
static __device__ __forceinline__ void st_cluster_v4_(unsigned addr, unsigned a, unsigned b,
                                                      unsigned c, unsigned d) {
    asm volatile("st.shared::cluster.v4.b32 [%0], {%1,%2,%3,%4};"
                 :: "r"(addr), "r"(a), "r"(b), "r"(c), "r"(d) : "memory");
}
// Release store: orders the preceding v4 slot-body store at cluster scope.
static __device__ __forceinline__ void st_release_cluster_b64_(unsigned addr, u64 v) {
    asm volatile("st.release.cluster.shared::cluster.b64 [%0], %1;"
                 :: "r"(addr), "l"(v) : "memory");
}
// Acquire load from LOCAL smem (data arrived via remote cluster stores).
static __device__ __forceinline__ u64 ld_acquire_cluster_b64_(unsigned addr) {
    u64 v;
    asm volatile("ld.acquire.cluster.shared::cta.b64 %0, [%1];"
                 : "=l"(v) : "r"(addr) : "memory");
    return v;
}
static __device__ __forceinline__ void cluster_sync_() {
    asm volatile("barrier.cluster.arrive.aligned;" ::: "memory");
    asm volatile("barrier.cluster.wait.aligned;" ::: "memory");
}

__global__ void __launch_bounds__(THREADS, 1) __cluster_dims__(CPB, 1, 1)
fps_kernel(const float* __restrict__ t_in, float* __restrict__ out)
{
    extern __shared__ float sm[];
    float* spx = sm;
    float* spy = sm + NPC;
    float* spz = sm + 2 * NPC;

    // Double-buffered slot exchange: [buf][src_rank][8 words]
    //  words 0-3: {val, idxf, x, y} (one st.v4)   words 4-5: b64 {lo=z, hi=flag=k}
    __shared__ __align__(16) unsigned s_slots[2][CPB][8];
    __shared__ unsigned s_v[NWARPS];
    __shared__ unsigned s_i[NWARPS];
    __shared__ unsigned s_bc[4];     // broadcast: {x, y, z, idxf}

    const int tid  = threadIdx.x;
    const int lane = tid & 31;
    const int warp = tid >> 5;
    const unsigned rank = cluster_rank_();
    const int batch = blockIdx.x / CPB;

    const float* __restrict__ pb = t_in + (size_t)batch * ((size_t)NPTS * 3);

    const unsigned slots_u32 = (unsigned)__cvta_generic_to_shared(&s_slots[0][0][0]);

    // Zero all slot words (flags start at 0 < first expected k=1).
    if (tid < 2 * CPB * 8) ((unsigned*)&s_slots[0][0][0])[tid] = 0u;

    // ---- load my 16 consecutive points into packed register pairs + smem copy ----
    const int base = (int)rank * NPC + tid * PPT;   // within-batch global index
    u64 px2[NPAIR], py2[NPAIR], pz2[NPAIR];
    float dist[PPT];
    {
        const float4* p4 = (const float4*)(pb + (size_t)base * 3);  // 192B aligned
        float c[PPT * 3];
        #pragma unroll
        for (int q = 0; q < (PPT * 3) / 4; q++) {
            float4 v = __ldg(p4 + q);
            c[4 * q + 0] = v.x; c[4 * q + 1] = v.y;
            c[4 * q + 2] = v.z; c[4 * q + 3] = v.w;
        }
        #pragma unroll
        for (int q = 0; q < NPAIR; q++) {
            px2[q] = pack2_(c[6 * q + 0], c[6 * q + 3]);
            py2[q] = pack2_(c[6 * q + 1], c[6 * q + 4]);
            pz2[q] = pack2_(c[6 * q + 2], c[6 * q + 5]);
        }
        #pragma unroll
        for (int j = 0; j < PPT; j++) {
            dist[j] = 1e10f;
            int li = tid * PPT + j;
            spx[li] = c[3 * j]; spy[li] = c[3 * j + 1]; spz[li] = c[3 * j + 2];
        }
    }

    // First sample is always index 0; its coords seed the loop.
    float lx = __ldg(pb + 0), ly = __ldg(pb + 1), lz = __ldg(pb + 2);
    if (rank == 0 && tid == 0) out[batch * NSAMP] = 0.0f;

    // Local flag init must be visible cluster-wide before any remote slot store.
    __syncthreads();
    cluster_sync_();

    for (int k = 1; k < NSAMP; k++) {
        // ---- packed distance update: 2 points per instruction ----
        const u64 nlx = pack2_(-lx, -lx);
        const u64 nly = pack2_(-ly, -ly);
        const u64 nlz = pack2_(-lz, -lz);

        unsigned bbits[PPT];
        #pragma unroll
        for (int q = 0; q < NPAIR; q++) {
            u64 dx2 = add2_(px2[q], nlx);
            u64 dy2 = add2_(py2[q], nly);
            u64 dz2 = add2_(pz2[q], nlz);
            // d = fma(dz,dz, fma(dy,dy, dx*dx)) per lane — bit-identical to ref.
            u64 d2  = fma2_(dz2, dz2, fma2_(dy2, dy2, mul2_(dx2, dx2)));
            float dlo, dhi;
            unpack2_(d2, dlo, dhi);
            float n0 = fminf(dist[2 * q + 0], dlo); dist[2 * q + 0] = n0;
            float n1 = fminf(dist[2 * q + 1], dhi); dist[2 * q + 1] = n1;
            bbits[2 * q + 0] = __float_as_uint(n0);   // dist>=0: uint order == float
            bbits[2 * q + 1] = __float_as_uint(n1);
        }

        // ---- per-thread argmax: uint max tree + parallel mask + ffs ----
        unsigned t0 = max(max(bbits[0],  bbits[1]),  max(bbits[2],  bbits[3]));
        unsigned t1 = max(max(bbits[4],  bbits[5]),  max(bbits[6],  bbits[7]));
        unsigned t2 = max(max(bbits[8],  bbits[9]),  max(bbits[10], bbits[11]));
        unsigned t3 = max(max(bbits[12], bbits[13]), max(bbits[14], bbits[15]));
        unsigned vb = max(max(t0, t1), max(t2, t3));
        unsigned msk = 0u;
        #pragma unroll
        for (int j = 0; j < PPT; j++)
            msk |= (bbits[j] == vb) ? (1u << j) : 0u;
        int bestj = __ffs(msk) - 1;                   // smallest j == first max
        int gidx  = base + bestj;

        // ---- warp argmax: redux + ballot + ffs (lowest lane == lowest index) ----
        unsigned vmax = __reduce_max_sync(0xffffffffu, vb);
        unsigned eq   = __ballot_sync(0xffffffffu, vb == vmax);
        int      src  = __ffs(eq) - 1;
        int      widx = __shfl_sync(0xffffffffu, gidx, src);
        if (lane == 0) { s_v[warp] = vmax; s_i[warp] = (unsigned)widx; }
        __syncthreads();

        const unsigned b = (unsigned)(k & 1);
        const unsigned sbase = slots_u32 + b * (CPB * 32u);

        // ---- warp 0: CTA argmax, push slot, poll flags, pick winner ----
        if (warp == 0) {
            unsigned v  = (lane < NWARPS) ? s_v[lane] : 0u;   // warps asc == index asc
            unsigned vm = __reduce_max_sync(0xffffffffu, v);
            unsigned e2 = __ballot_sync(0xffffffffu, v == vm);
            int      s2 = __ffs(e2) - 1;
            unsigned cidx = s_i[s2];                          // CTA winner index

            if (lane < CPB) {
                int li = (int)cidx - (int)rank * NPC;         // winner is CTA-local
                unsigned xb = __float_as_uint(spx[li]);
                unsigned yb = __float_as_uint(spy[li]);
                unsigned zb = __float_as_uint(spz[li]);
                unsigned la = sbase + rank * 32u;
                unsigned ra = mapa_shared_(la, (unsigned)lane);
                st_cluster_v4_(ra, vm, __float_as_uint(__uint2float_rn(cidx)), xb, yb);
                // release store of {z, flag=k} orders the v4 body before it
                st_release_cluster_b64_(ra + 16u, ((u64)(unsigned)k << 32) | (u64)zb);
            }

            // Poll: lane i watches slot i's flag (32 threads total — no L1 thrash).
            unsigned zw = 0u, bal;
            do {
                unsigned done = 1u;
                if (lane < CPB) {
                    u64 w = ld_acquire_cluster_b64_(sbase + lane * 32u + 16u);
                    done = ((unsigned)(w >> 32) == (unsigned)k) ? 1u : 0u;
                    zw   = (unsigned)(w & 0xffffffffu);
                }
                bal = __ballot_sync(0xffffffffu, done != 0u);
            } while (bal != 0xffffffffu);

            // Winner over the 8 slots (lane i holds slot i's data).
            unsigned val = 0u, idxf = 0u, xw = 0u, yw = 0u;
            if (lane < CPB) {
                const unsigned* sp = &s_slots[b][lane][0];
                val = sp[0]; idxf = sp[1]; xw = sp[2]; yw = sp[3];
            }
            unsigned wm = __reduce_max_sync(0xffffffffu, val);
            unsigned we = __ballot_sync(0xffffffffu, (lane < CPB) && (val == wm));
            int      wl = __ffs(we) - 1;                      // lowest rank wins tie
            unsigned bi = __shfl_sync(0xffffffffu, idxf, wl);
            unsigned bx = __shfl_sync(0xffffffffu, xw,   wl);
            unsigned by = __shfl_sync(0xffffffffu, yw,   wl);
            unsigned bz = __shfl_sync(0xffffffffu, zw,   wl);
            if (lane == 0) {
                s_bc[0] = bx; s_bc[1] = by; s_bc[2] = bz; s_bc[3] = bi;
                if (rank == 0) out[batch * NSAMP + k] = __uint_as_float(bi);
            }
        }
        __syncthreads();

        lx = __uint_as_float(s_bc[0]);
        ly = __uint_as_float(s_bc[1]);
        lz = __uint_as_float(s_bc[2]);
    }

    // Defensive: no CTA exits while peers could still address its smem.
    cluster_sync_();
}

extern "C" void kernel_launch(void* const* d_in, const int* in_sizes, int n_in,
                              void* d_out, int out_size)
{
    // t_in is the largest input under any size convention.
    int best = 0;
    for (int i = 1; i < n_in; i++)
        if (in_sizes[i] > in_sizes[best]) best = i;
    const float* t_in = (const float*)d_in[best];

    // Not a stream op; graph-capture safe.
    cudaFuncSetAttribute(fps_kernel, cudaFuncAttributeMaxDynamicSharedMemorySize,
                         SMEM_BYTES);

    fps_kernel<<<BATCHES * CPB, THREADS, SMEM_BYTES>>>(t_in, (float*)d_out);
}

// round 17
// speedup vs baseline: 1.1467x; 1.0262x over previous
#include <cuda_runtime.h>
#include <cstdint>
#include <cstddef>

#define BATCHES 16
#define NPTS    65536
#define NSAMP   2048
#define CPB     8                    // CTAs per batch = cluster size
#define NPC     (NPTS / CPB)         // 8192 points per CTA
#define THREADS 512
#define NWARPS  (THREADS / 32)       // 16
#define PPT     (NPC / THREADS)      // 16 consecutive points per thread
#define NPAIR   (PPT / 2)            // 8 packed point-pairs per thread

// dynamic smem: local copy of this CTA's coords (winner lookup only)
#define SMEM_BYTES (3 * NPC * 4)     // 96 KB

typedef unsigned long long u64;

// ---- packed f32x2 helpers (per-lane IEEE .rn — bit-identical to scalar) ----
static __device__ __forceinline__ u64 pack2_(float lo, float hi) {
    u64 r; asm("mov.b64 %0, {%1, %2};" : "=l"(r) : "f"(lo), "f"(hi)); return r;
}
static __device__ __forceinline__ void unpack2_(u64 v, float& lo, float& hi) {
    asm("mov.b64 {%0, %1}, %2;" : "=f"(lo), "=f"(hi) : "l"(v));
}
static __device__ __forceinline__ u64 add2_(u64 a, u64 b) {
    u64 r; asm("add.rn.f32x2 %0, %1, %2;" : "=l"(r) : "l"(a), "l"(b)); return r;
}
static __device__ __forceinline__ u64 mul2_(u64 a, u64 b) {
    u64 r; asm("mul.rn.f32x2 %0, %1, %2;" : "=l"(r) : "l"(a), "l"(b)); return r;
}
static __device__ __forceinline__ u64 fma2_(u64 a, u64 b, u64 c) {
    u64 r; asm("fma.rn.f32x2 %0, %1, %2, %3;" : "=l"(r) : "l"(a), "l"(b), "l"(c)); return r;
}

static __device__ __forceinline__ unsigned cluster_rank_() {
    unsigned r;
    asm("mov.u32 %0, %%cluster_ctarank;" : "=r"(r));
    return r;
}
static __device__ __forceinline__ unsigned mapa_shared_(unsigned addr, unsigned target) {
    unsigned r;
    asm("mapa.shared::cluster.u32 %0, %1, %2;" : "=r"(r) : "r"(addr), "r"(target));
    return r;
}
static __device__ __forceinline__ void st_cluster_v4_(unsigned addr, unsigned a, unsigned b,
                                                      unsigned c, unsigned d) {
    asm volatile("st.shared::cluster.v4.b32 [%0], {%1,%2,%3,%4};"
                 :: "r"(addr), "r"(a), "r"(b), "r"(c), "r"(d) : "memory");
}
static __device__ __forceinline__ void st_cluster_b32_(unsigned addr, unsigned a) {
    asm volatile("st.shared::cluster.b32 [%0], %1;"
                 :: "r"(addr), "r"(a) : "memory");
}
static __device__ __forceinline__ void cluster_arrive_() {
    asm volatile("barrier.cluster.arrive.aligned;" ::: "memory");
}
static __device__ __forceinline__ void cluster_wait_() {
    asm volatile("barrier.cluster.wait.aligned;" ::: "memory");
}
// Named-barrier producer/consumer split (barrier id 1, full CTA count).
static __device__ __forceinline__ void bar_arrive_1_() {
    asm volatile("bar.arrive 1, %0;" :: "n"(THREADS) : "memory");
}
static __device__ __forceinline__ void bar_sync_1_() {
    asm volatile("bar.sync 1, %0;" :: "n"(THREADS) : "memory");
}

__global__ void __launch_bounds__(THREADS, 1) __cluster_dims__(CPB, 1, 1)
fps_kernel(const float* __restrict__ t_in, float* __restrict__ out)
{
    extern __shared__ float sm[];
    float* spx = sm;
    float* spy = sm + NPC;
    float* spz = sm + 2 * NPC;

    // Double-buffered cluster slot exchange: [buf][src_rank][8] = {val, idxf, x, y, z,...}
    __shared__ __align__(16) float s_slots[2][CPB][8];
    __shared__ __align__(8)  u64   s_vi[NWARPS];     // packed (val<<32)|idx per warp

    const int tid  = threadIdx.x;
    const int lane = tid & 31;
    const int warp = tid >> 5;
    const unsigned rank = cluster_rank_();
    const int batch = blockIdx.x / CPB;

    const float* __restrict__ pb = t_in + (size_t)batch * ((size_t)NPTS * 3);

    // ---- load my 16 consecutive points into packed register pairs + smem copy ----
    const int base = (int)rank * NPC + tid * PPT;   // within-batch global index
    u64 px2[NPAIR], py2[NPAIR], pz2[NPAIR];
    float dist[PPT];
    {
        const float4* p4 = (const float4*)(pb + (size_t)base * 3);  // 192B aligned
        float c[PPT * 3];
        #pragma unroll
        for (int q = 0; q < (PPT * 3) / 4; q++) {
            float4 v = __ldg(p4 + q);
            c[4 * q + 0] = v.x; c[4 * q + 1] = v.y;
            c[4 * q + 2] = v.z; c[4 * q + 3] = v.w;
        }
        #pragma unroll
        for (int q = 0; q < NPAIR; q++) {
            px2[q] = pack2_(c[6 * q + 0], c[6 * q + 3]);
            py2[q] = pack2_(c[6 * q + 1], c[6 * q + 4]);
            pz2[q] = pack2_(c[6 * q + 2], c[6 * q + 5]);
        }
        #pragma unroll
        for (int j = 0; j < PPT; j++) {
            dist[j] = 1e10f;
            int li = tid * PPT + j;
            spx[li] = c[3 * j]; spy[li] = c[3 * j + 1]; spz[li] = c[3 * j + 2];
        }
    }

    // First sample is always index 0; its coords seed the loop.
    float lx = __ldg(pb + 0), ly = __ldg(pb + 1), lz = __ldg(pb + 2);
    if (rank == 0 && tid == 0) out[batch * NSAMP] = 0.0f;
    __syncthreads();

    const unsigned slots_u32 =
        (unsigned)__cvta_generic_to_shared(&s_slots[0][0][0]);

    for (int k = 1; k < NSAMP; k++) {
        // ---- packed distance update: 2 points per instruction ----
        const u64 nlx = pack2_(-lx, -lx);
        const u64 nly = pack2_(-ly, -ly);
        const u64 nlz = pack2_(-lz, -lz);

        unsigned bbits[PPT];
        #pragma unroll
        for (int q = 0; q < NPAIR; q++) {
            u64 dx2 = add2_(px2[q], nlx);
            u64 dy2 = add2_(py2[q], nly);
            u64 dz2 = add2_(pz2[q], nlz);
            // d = fma(dz,dz, fma(dy,dy, dx*dx)) per lane — bit-identical to ref.
            u64 d2  = fma2_(dz2, dz2, fma2_(dy2, dy2, mul2_(dx2, dx2)));
            float dlo, dhi;
            unpack2_(d2, dlo, dhi);
            float n0 = fminf(dist[2 * q + 0], dlo); dist[2 * q + 0] = n0;
            float n1 = fminf(dist[2 * q + 1], dhi); dist[2 * q + 1] = n1;
            bbits[2 * q + 0] = __float_as_uint(n0);   // dist>=0: uint order == float
            bbits[2 * q + 1] = __float_as_uint(n1);
        }

        // ---- per-thread argmax: uint max tree + parallel mask + ffs ----
        unsigned t0 = max(max(bbits[0],  bbits[1]),  max(bbits[2],  bbits[3]));
        unsigned t1 = max(max(bbits[4],  bbits[5]),  max(bbits[6],  bbits[7]));
        unsigned t2 = max(max(bbits[8],  bbits[9]),  max(bbits[10], bbits[11]));
        unsigned t3 = max(max(bbits[12], bbits[13]), max(bbits[14], bbits[15]));
        unsigned vb = max(max(t0, t1), max(t2, t3));
        unsigned msk = 0u;
        #pragma unroll
        for (int j = 0; j < PPT; j++)
            msk |= (bbits[j] == vb) ? (1u << j) : 0u;
        int bestj = __ffs(msk) - 1;                   // smallest j == first max
        int gidx  = base + bestj;

        // ---- warp argmax: redux + ballot + ffs (lowest lane == lowest index) ----
        unsigned vmax = __reduce_max_sync(0xffffffffu, vb);
        unsigned eq   = __ballot_sync(0xffffffffu, vb == vmax);
        int      src  = __ffs(eq) - 1;
        int      widx = __shfl_sync(0xffffffffu, gidx, src);
        if (lane == 0)
            s_vi[warp] = ((u64)vmax << 32) | (u64)(unsigned)widx;   // one STS.64

        // ---- producer/consumer split: non-zero warps park at the cluster barrier ----
        if (warp != 0) {
            bar_arrive_1_();          // signal winner stored (non-blocking)
            cluster_arrive_();        // own stores (none pending) — arrival only
            cluster_wait_();          // sleep until all CTAs' warp 0 arrive
        } else {
            bar_sync_1_();            // wait for all 15 producers' STS.64

            u64 wv = (lane < NWARPS) ? s_vi[lane] : 0ull;           // one LDS.64
            unsigned v = (unsigned)(wv >> 32);
            unsigned vm = __reduce_max_sync(0xffffffffu, v);
            unsigned e2 = __ballot_sync(0xffffffffu, v == vm);
            int      s2 = __ffs(e2) - 1;                            // warps asc == idx asc
            unsigned cidx = (unsigned)__shfl_sync(0xffffffffu, (unsigned)(wv & 0xffffffffu), s2);

            if (lane < CPB) {
                int li = (int)cidx - (int)rank * NPC;               // winner is CTA-local
                unsigned xb = __float_as_uint(spx[li]);
                unsigned yb = __float_as_uint(spy[li]);
                unsigned zb = __float_as_uint(spz[li]);
                unsigned la = slots_u32 + (((unsigned)(k & 1) * CPB + rank) * 8u) * 4u;
                unsigned ra = mapa_shared_(la, (unsigned)lane);
                st_cluster_v4_(ra, vm, __float_as_uint(__uint2float_rn(cidx)), xb, yb);
                st_cluster_b32_(ra + 16u, zb);
            }
            cluster_arrive_();        // releases the DSMEM stores above
            cluster_wait_();
        }

        // ---- all threads: tree-scan the 8 local slots for the batch winner ----
        const unsigned* ss = (const unsigned*)&s_slots[k & 1][0][0];
        unsigned sv[CPB];
        #pragma unroll
        for (int s = 0; s < CPB; s++) sv[s] = ss[s * 8];
        unsigned u01 = max(sv[0], sv[1]);
        unsigned u23 = max(sv[2], sv[3]);
        unsigned u45 = max(sv[4], sv[5]);
        unsigned u67 = max(sv[6], sv[7]);
        unsigned umx = max(max(u01, u23), max(u45, u67));
        unsigned sm2 = 0u;
        #pragma unroll
        for (int s = 0; s < CPB; s++)
            sm2 |= (sv[s] == umx) ? (1u << s) : 0u;
        int bs = __ffs(sm2) - 1;                      // lowest rank wins tie

        const float* w = &s_slots[k & 1][bs][0];
        lx = w[2]; ly = w[3]; lz = w[4];

        if (rank == 0 && tid == 0) out[batch * NSAMP + k] = w[1];
    }
}

extern "C" void kernel_launch(void* const* d_in, const int* in_sizes, int n_in,
                              void* d_out, int out_size)
{
    // t_in is the largest input under any size convention.
    int best = 0;
    for (int i = 1; i < n_in; i++)
        if (in_sizes[i] > in_sizes[best]) best = i;
    const float* t_in = (const float*)d_in[best];

    // Not a stream op; graph-capture safe.
    cudaFuncSetAttribute(fps_kernel, cudaFuncAttributeMaxDynamicSharedMemorySize,
                         SMEM_BYTES);

    fps_kernel<<<BATCHES * CPB, THREADS, SMEM_BYTES>>>(t_in, (float*)d_out);
}